// round 10
// baseline (speedup 1.0000x reference)
#include <cuda_runtime.h>
#include <cuda_bf16.h>
#include <cstdint>

#define D        256
#define NMAX     8192
#define BM       128
#define BN       128
#define KSPLIT   2
#define NKEYS    (NMAX / KSPLIT)         // 4096 keys per CTA
#define NT       (NKEYS / BN)            // 32 key tiles
#define GRID_SZ  ((NMAX / BM) * KSPLIT)  // 128 CTAs, one wave
#define THREADS  256                     // 8 warps, warp grid 4(M) x 2(N)
#define SPAD     264                     // 256 + 8 halves pad: conflict-free LDSM

#define LOG2E    1.4426950408889634f
#define LN2      0.6931471805599453f

// smem: [0..31] mbarriers (full0, full1, empty0, empty1), data from 128
#define MB_FULL0   0
#define MB_FULL1   8
#define MB_EMPTY0  16
#define MB_EMPTY1  24
#define DATA_OFF   128

__device__ __align__(16) __nv_bfloat16 g_Qn[(size_t)NMAX * D];
__device__ __align__(16) __nv_bfloat16 g_Kn[(size_t)NMAX * D];
__device__ float g_psum[NMAX * KSPLIT];
__device__ float g_pdiag[NMAX * KSPLIT];

// ---------------- helpers ----------------
__device__ __forceinline__ void cp_async16(void* smem_dst, const void* gmem_src) {
    uint32_t s = (uint32_t)__cvta_generic_to_shared(smem_dst);
    asm volatile("cp.async.cg.shared.global [%0], [%1], 16;\n" :: "r"(s), "l"(gmem_src));
}
// .noinc: one REAL arrival per thread (init count == #threads).
__device__ __forceinline__ void cp_mbar_arrive_noinc(uint32_t mbar) {
    asm volatile("cp.async.mbarrier.arrive.noinc.shared::cta.b64 [%0];"
                 :: "r"(mbar) : "memory");
}
__device__ __forceinline__ void mbar_init(uint32_t a, uint32_t cnt) {
    asm volatile("mbarrier.init.shared.b64 [%0], %1;" :: "r"(a), "r"(cnt) : "memory");
}
__device__ __forceinline__ void mbar_arrive(uint32_t a) {
    asm volatile("mbarrier.arrive.shared.b64 _, [%0];" :: "r"(a) : "memory");
}
__device__ __forceinline__ void mbar_wait(uint32_t a, uint32_t parity) {
    asm volatile("{\n\t.reg .pred P1;\n\t"
                 "WAIT_LOOP_%=:\n\t"
                 "mbarrier.try_wait.parity.acquire.cta.shared::cta.b64 P1, [%0], %1, 0x989680;\n\t"
                 "@P1 bra.uni WAIT_DONE_%=;\n\t"
                 "bra.uni WAIT_LOOP_%=;\n\t"
                 "WAIT_DONE_%=:\n\t}" :: "r"(a), "r"(parity) : "memory");
}
__device__ __forceinline__ void ldsm_x4(uint32_t& r0, uint32_t& r1,
                                        uint32_t& r2, uint32_t& r3, uint32_t addr) {
    asm volatile("ldmatrix.sync.aligned.m8n8.x4.shared.b16 {%0,%1,%2,%3}, [%4];"
                 : "=r"(r0), "=r"(r1), "=r"(r2), "=r"(r3) : "r"(addr));
}
__device__ __forceinline__ float exp2_fast(float x) {
    float r;
    asm("ex2.approx.ftz.f32 %0, %1;" : "=f"(r) : "f"(x));
    return r;
}

// Load one [128 x 256 bf16] tile into SPAD-padded smem via cp.async (256 thr).
__device__ __forceinline__ void load_tile_async(__nv_bfloat16* s,
                                                const __nv_bfloat16* g, int tid) {
    const uint4* src = (const uint4*)g;
    #pragma unroll
    for (int i = tid; i < BM * 32; i += THREADS) {   // 32 x 16B chunks per row
        int r = i >> 5, c = i & 31;
        cp_async16(s + r * SPAD + c * 8, src + r * 32 + c);
    }
}

// ---------------------------------------------------------------------------
// Kernel 1: L2 normalize; one warp per row; queries get 2*log2(e) folded in
// (log2-domain logits, |logit| <= 2.89 -> no max tracking anywhere).
// ---------------------------------------------------------------------------
__global__ void normalize_kernel(const float* __restrict__ q,
                                 const float* __restrict__ k, int N) {
    const int warp = threadIdx.x >> 5, lane = threadIdx.x & 31;
    const int row  = blockIdx.x * 8 + warp;          // grid = 2N/8
    const bool is_q = row < N;
    const int  r    = is_q ? row : row - N;
    const float4* src = (const float4*)((is_q ? q : k) + (size_t)r * D);
    uint4* dst = (uint4*)((is_q ? g_Qn : g_Kn) + (size_t)r * D);

    float4 v0 = src[lane * 2], v1 = src[lane * 2 + 1];
    float ss = v0.x*v0.x + v0.y*v0.y + v0.z*v0.z + v0.w*v0.w
             + v1.x*v1.x + v1.y*v1.y + v1.z*v1.z + v1.w*v1.w;
    #pragma unroll
    for (int o = 16; o > 0; o >>= 1) ss += __shfl_xor_sync(0xffffffffu, ss, o);

    float scale = rsqrtf(fmaxf(ss, 1e-24f));
    if (is_q) scale *= 2.0f * LOG2E;    // 1/temperature + log2 domain

    __nv_bfloat162 b0 = __float22bfloat162_rn({v0.x*scale, v0.y*scale});
    __nv_bfloat162 b1 = __float22bfloat162_rn({v0.z*scale, v0.w*scale});
    __nv_bfloat162 b2 = __float22bfloat162_rn({v1.x*scale, v1.y*scale});
    __nv_bfloat162 b3 = __float22bfloat162_rn({v1.z*scale, v1.w*scale});
    uint4 o;
    o.x = *(uint32_t*)&b0; o.y = *(uint32_t*)&b1;
    o.z = *(uint32_t*)&b2; o.w = *(uint32_t*)&b3;
    dst[lane] = o;
}

// ---------------------------------------------------------------------------
// Kernel 2: bf16 mma.sync GEMM + fused sum(2^logit). 256 thr (8 warps),
// warp grid 4(M) x 2(N), warp tile 32x64. mbarrier-paced double buffer.
// Epilogue of tile t-1 (64 ex2, register-only) is software-pipelined INTO
// tile t's ks-loop (4/iter) so MUFU hides under MMA/LDSM. 256 threads ->
// 255-reg ceiling, so the pacc[64] snapshot fits without spilling (the
// 512-thread/128-reg variant of this regressed in R8).
// ---------------------------------------------------------------------------
__global__ __launch_bounds__(THREADS, 1)
void infonce_kernel() {
    extern __shared__ __align__(16) char smem_raw[];
    const uint32_t sb = (uint32_t)__cvta_generic_to_shared(smem_raw);
    __nv_bfloat16* As  = (__nv_bfloat16*)(smem_raw + DATA_OFF); // 128 * SPAD
    __nv_bfloat16* Bs0 = As + BM * SPAD;                        // buf 0
    __nv_bfloat16* Bs1 = Bs0 + BN * SPAD;                       // buf 1
    __nv_bfloat16* Bbuf[2] = { Bs0, Bs1 };

    const uint32_t full_mb[2]  = { sb + MB_FULL0,  sb + MB_FULL1 };
    const uint32_t empty_mb[2] = { sb + MB_EMPTY0, sb + MB_EMPTY1 };

    const int tid    = threadIdx.x;
    const int lane   = tid & 31;
    const int warp   = tid >> 5;
    const int warp_m = warp >> 1;       // 0..3 (32 rows each)
    const int warp_n = warp & 1;        // 0..1 (64 cols each)

    const int qb    = blockIdx.x / KSPLIT;
    const int split = blockIdx.x % KSPLIT;
    const int qr0   = qb * BM;
    const int kv0   = split * NKEYS;

    if (tid == 0) {
        mbar_init(full_mb[0], THREADS);  mbar_init(full_mb[1], THREADS);
        mbar_init(empty_mb[0], 8);       mbar_init(empty_mb[1], 8);
    }
    __syncthreads();

    // prologue: A + tile0 -> buf0
    load_tile_async(As, g_Qn + (size_t)qr0 * D, tid);
    load_tile_async(Bs0, g_Kn + (size_t)kv0 * D, tid);
    cp_mbar_arrive_noinc(full_mb[0]);

    // ldmatrix addresses
    uint32_t a_base[2];
    #pragma unroll
    for (int mt = 0; mt < 2; ++mt)
        a_base[mt] = (uint32_t)__cvta_generic_to_shared(
            As + (warp_m * 32 + mt * 16 + (lane & 15)) * SPAD + (lane >> 4) * 8);
    uint32_t b_row_off[4];                // 4 x 16-col groups = 64 cols per warp
    #pragma unroll
    for (int b = 0; b < 4; ++b)
        b_row_off[b] = (uint32_t)(
            ((warp_n * 64 + b * 16 + ((lane >> 4) & 1) * 8 + (lane & 7)) * SPAD
             + ((lane >> 3) & 1) * 8) * sizeof(__nv_bfloat16));

    const bool cta_has_diag = (qr0 >= kv0) && (qr0 < kv0 + NKEYS);
    const int  kt_diag      = (qr0 - kv0) >> 7;

    // parities: full waits start {0,0}; empty waits start {0,1}
    uint32_t cf0 = 0, cf1 = 0, pe0 = 0, pe1 = 1;

    float rsum[4]  = {0.f, 0.f, 0.f, 0.f};
    float rdiag[4] = {0.f, 0.f, 0.f, 0.f};
    float pacc[64];                       // prev tile accumulator snapshot

    for (int kt = 0; kt < NT; ++kt) {
        const int b  = kt & 1;
        const int nb = b ^ 1;

        // producer: prefetch tile kt+1 into buf nb
        if (kt + 1 < NT) {
            uint32_t pe = nb ? pe1 : pe0;
            mbar_wait(empty_mb[nb], pe);
            if (nb) pe1 ^= 1; else pe0 ^= 1;
            load_tile_async(Bbuf[nb], g_Kn + (size_t)(kv0 + (kt + 1) * BN) * D, tid);
            cp_mbar_arrive_noinc(full_mb[nb]);
        }

        // consumer: tile kt data fully visible
        {
            uint32_t cf = b ? cf1 : cf0;
            mbar_wait(full_mb[b], cf);
            if (b) cf1 ^= 1; else cf0 ^= 1;
        }

        float acc[2][8][4];
        #pragma unroll
        for (int a = 0; a < 2; ++a)
            #pragma unroll
            for (int bb2 = 0; bb2 < 8; ++bb2)
                #pragma unroll
                for (int c = 0; c < 4; ++c) acc[a][bb2][c] = 0.f;

        const uint32_t bb = (uint32_t)__cvta_generic_to_shared(Bbuf[b]);
        const bool flush = (kt > 0);

        #pragma unroll
        for (int ks = 0; ks < D / 16; ++ks) {
            uint32_t af[2][4], bf[16];
            ldsm_x4(af[0][0], af[0][1], af[0][2], af[0][3], a_base[0] + ks * 32);
            ldsm_x4(af[1][0], af[1][1], af[1][2], af[1][3], a_base[1] + ks * 32);
            #pragma unroll
            for (int g = 0; g < 4; ++g)
                ldsm_x4(bf[g * 4], bf[g * 4 + 1], bf[g * 4 + 2], bf[g * 4 + 3],
                        bb + b_row_off[g] + ks * 32);

            // interleaved epilogue of tile kt-1: 4 ex2+add per ks iteration
            // (MUFU pipe, register-only -> hides under LDSM->HMMA latency)
            if (flush) {
                #pragma unroll
                for (int u = 0; u < 4; ++u) {
                    const int idx = ks * 4 + u;              // 0..63
                    const int c = idx & 3;
                    rsum[(idx >> 5) * 2 + (c >> 1)] += exp2_fast(pacc[idx]);
                }
            }

            #pragma unroll
            for (int mt = 0; mt < 2; ++mt)
                #pragma unroll
                for (int nt = 0; nt < 8; ++nt) {
                    asm volatile(
                        "mma.sync.aligned.m16n8k16.row.col.f32.bf16.bf16.f32 "
                        "{%0,%1,%2,%3}, {%4,%5,%6,%7}, {%8,%9}, {%0,%1,%2,%3};\n"
                        : "+f"(acc[mt][nt][0]), "+f"(acc[mt][nt][1]),
                          "+f"(acc[mt][nt][2]), "+f"(acc[mt][nt][3])
                        : "r"(af[mt][0]), "r"(af[mt][1]),
                          "r"(af[mt][2]), "r"(af[mt][3]),
                          "r"(bf[nt * 2]), "r"(bf[nt * 2 + 1]));
                }
        }

        // done reading buf b -> producers may overwrite it
        if (lane == 0) mbar_arrive(empty_mb[b]);

        // snapshot acc -> pacc (epilogue deferred into next tile's ks loop)
        #pragma unroll
        for (int mt = 0; mt < 2; ++mt)
            #pragma unroll
            for (int nt = 0; nt < 8; ++nt)
                #pragma unroll
                for (int c = 0; c < 4; ++c)
                    pacc[mt * 32 + nt * 4 + c] = acc[mt][nt][c];

        // diagonal capture (one tile per CTA; outside the hot path)
        if (cta_has_diag && kt == kt_diag) {
            #pragma unroll
            for (int mt = 0; mt < 2; ++mt)
                #pragma unroll
                for (int nt = 0; nt < 8; ++nt)
                    #pragma unroll
                    for (int c = 0; c < 4; ++c) {
                        int lr = warp_m * 32 + mt * 16 + (c >> 1) * 8 + (lane >> 2);
                        int lc = warp_n * 64 + nt * 8 + (lane & 3) * 2 + (c & 1);
                        if (lr == lc) rdiag[mt * 2 + (c >> 1)] += acc[mt][nt][c];
                    }
        }
    }

    // flush final tile's epilogue
    #pragma unroll
    for (int idx = 0; idx < 64; ++idx) {
        const int c = idx & 3;
        rsum[(idx >> 5) * 2 + (c >> 1)] += exp2_fast(pacc[idx]);
    }

    // reduce: quad lanes share each row; then 2 n-warps per row via smem
    #pragma unroll
    for (int rs = 0; rs < 4; ++rs) {
        rsum[rs]  += __shfl_xor_sync(0xffffffffu, rsum[rs], 1);
        rsum[rs]  += __shfl_xor_sync(0xffffffffu, rsum[rs], 2);
        rdiag[rs] += __shfl_xor_sync(0xffffffffu, rdiag[rs], 1);
        rdiag[rs] += __shfl_xor_sync(0xffffffffu, rdiag[rs], 2);
    }
    __syncthreads();                       // B buffers free now
    float* s_sum = (float*)Bs0;            // [BM][2]
    float* s_dg  = s_sum + BM * 2;
    if ((lane & 3) == 0) {
        #pragma unroll
        for (int rs = 0; rs < 4; ++rs) {
            int lr = warp_m * 32 + (rs >> 1) * 16 + (rs & 1) * 8 + (lane >> 2);
            s_sum[lr * 2 + warp_n] = rsum[rs];
            s_dg [lr * 2 + warp_n] = rdiag[rs];
        }
    }
    __syncthreads();
    if (tid < BM) {
        float s = s_sum[tid * 2] + s_sum[tid * 2 + 1];
        float d = s_dg [tid * 2] + s_dg [tid * 2 + 1];
        int gr = qr0 + tid;
        g_psum [gr * KSPLIT + split] = s;
        g_pdiag[gr * KSPLIT + split] = d;
    }
}

// ---------------------------------------------------------------------------
// Kernel 3: finalize. loss = mean( ln2 * (log2(sum splits) - diag_log2) )
// ---------------------------------------------------------------------------
__global__ void finalize_kernel(float* __restrict__ out) {
    __shared__ float wsum[8];
    float acc = 0.f;
    for (int r = blockIdx.x * 256 + threadIdx.x; r < NMAX; r += gridDim.x * 256) {
        float s = 0.f, d = 0.f;
        #pragma unroll
        for (int k = 0; k < KSPLIT; ++k) {
            s += g_psum [r * KSPLIT + k];
            d += g_pdiag[r * KSPLIT + k];
        }
        acc += LN2 * (log2f(s) - d);
    }
    #pragma unroll
    for (int o = 16; o > 0; o >>= 1) acc += __shfl_xor_sync(0xffffffffu, acc, o);
    if ((threadIdx.x & 31) == 0) wsum[threadIdx.x >> 5] = acc;
    __syncthreads();
    if (threadIdx.x == 0) {
        float t = 0.f;
        #pragma unroll
        for (int i = 0; i < 8; ++i) t += wsum[i];
        atomicAdd(out, t / (float)NMAX);
    }
}

// ---------------------------------------------------------------------------
extern "C" void kernel_launch(void* const* d_in, const int* in_sizes, int n_in,
                              void* d_out, int out_size) {
    const float* q = (const float*)d_in[0];
    const float* k = (const float*)d_in[1];
    const int N = in_sizes[0] / D;          // 8192
    float* out = (float*)d_out;

    cudaMemsetAsync(out, 0, sizeof(float), 0);   // atomicAdd accumulator

    normalize_kernel<<<2 * N / 8, 256>>>(q, k, N);

    size_t smem = DATA_OFF + (size_t)(BM + 2 * BN) * SPAD * sizeof(__nv_bfloat16);
    cudaFuncSetAttribute(infonce_kernel,
                         cudaFuncAttributeMaxDynamicSharedMemorySize, (int)smem);
    infonce_kernel<<<GRID_SZ, THREADS, smem>>>();

    finalize_kernel<<<16, 256>>>(out);
}

// round 11
// speedup vs baseline: 1.0393x; 1.0393x over previous
#include <cuda_runtime.h>
#include <cuda_bf16.h>
#include <cstdint>

#define D        256
#define NMAX     8192
#define BM       128
#define BN       128
#define KSPLIT   2
#define NKEYS    (NMAX / KSPLIT)         // 4096 keys per CTA
#define NT       (NKEYS / BN)            // 32 key tiles
#define GRID_SZ  ((NMAX / BM) * KSPLIT)  // 128 CTAs, one wave
#define THREADS  256                     // 8 warps, warp grid 4(M) x 2(N)
#define SPAD     264                     // 256 + 8 halves pad: conflict-free LDSM

#define LOG2E    1.4426950408889634f
#define LN2      0.6931471805599453f

// smem: [0..31] mbarriers (full0, full1, empty0, empty1), data from 128
#define MB_FULL0   0
#define MB_FULL1   8
#define MB_EMPTY0  16
#define MB_EMPTY1  24
#define DATA_OFF   128

__device__ __align__(16) __nv_bfloat16 g_Qn[(size_t)NMAX * D];
__device__ __align__(16) __nv_bfloat16 g_Kn[(size_t)NMAX * D];
__device__ float g_psum[NMAX * KSPLIT];
__device__ float g_pdiag[NMAX * KSPLIT];

// ---------------- helpers ----------------
__device__ __forceinline__ void cp_async16(void* smem_dst, const void* gmem_src) {
    uint32_t s = (uint32_t)__cvta_generic_to_shared(smem_dst);
    asm volatile("cp.async.cg.shared.global [%0], [%1], 16;\n" :: "r"(s), "l"(gmem_src));
}
// .noinc: one REAL arrival per thread (init count == #threads).
__device__ __forceinline__ void cp_mbar_arrive_noinc(uint32_t mbar) {
    asm volatile("cp.async.mbarrier.arrive.noinc.shared::cta.b64 [%0];"
                 :: "r"(mbar) : "memory");
}
__device__ __forceinline__ void mbar_init(uint32_t a, uint32_t cnt) {
    asm volatile("mbarrier.init.shared.b64 [%0], %1;" :: "r"(a), "r"(cnt) : "memory");
}
__device__ __forceinline__ void mbar_arrive(uint32_t a) {
    asm volatile("mbarrier.arrive.shared.b64 _, [%0];" :: "r"(a) : "memory");
}
__device__ __forceinline__ void mbar_wait(uint32_t a, uint32_t parity) {
    asm volatile("{\n\t.reg .pred P1;\n\t"
                 "WAIT_LOOP_%=:\n\t"
                 "mbarrier.try_wait.parity.acquire.cta.shared::cta.b64 P1, [%0], %1, 0x989680;\n\t"
                 "@P1 bra.uni WAIT_DONE_%=;\n\t"
                 "bra.uni WAIT_LOOP_%=;\n\t"
                 "WAIT_DONE_%=:\n\t}" :: "r"(a), "r"(parity) : "memory");
}
__device__ __forceinline__ void ldsm_x4(uint32_t& r0, uint32_t& r1,
                                        uint32_t& r2, uint32_t& r3, uint32_t addr) {
    asm volatile("ldmatrix.sync.aligned.m8n8.x4.shared.b16 {%0,%1,%2,%3}, [%4];"
                 : "=r"(r0), "=r"(r1), "=r"(r2), "=r"(r3) : "r"(addr));
}
__device__ __forceinline__ float exp2_fast(float x) {
    float r;
    asm("ex2.approx.ftz.f32 %0, %1;" : "=f"(r) : "f"(x));
    return r;
}

// Load one [128 x 256 bf16] tile into SPAD-padded smem via cp.async (256 thr).
__device__ __forceinline__ void load_tile_async(__nv_bfloat16* s,
                                                const __nv_bfloat16* g, int tid) {
    const uint4* src = (const uint4*)g;
    #pragma unroll
    for (int i = tid; i < BM * 32; i += THREADS) {   // 32 x 16B chunks per row
        int r = i >> 5, c = i & 31;
        cp_async16(s + r * SPAD + c * 8, src + r * 32 + c);
    }
}

// ---------------------------------------------------------------------------
// Kernel 1: L2 normalize; one warp per TWO rows (interleaved reductions for
// ILP); queries get 2*log2(e) folded in -> log2-domain logits, no max needed.
// N even and row pairs aligned -> a pair never straddles the q/k boundary.
// ---------------------------------------------------------------------------
__global__ void normalize_kernel(const float* __restrict__ q,
                                 const float* __restrict__ k, int N) {
    const int warp = threadIdx.x >> 5, lane = threadIdx.x & 31;
    const int row0 = blockIdx.x * 16 + warp * 2;     // grid = 2N/16
    const bool is_q = row0 < N;
    const int  r0   = is_q ? row0 : row0 - N;
    const float* srcb = is_q ? q : k;
    __nv_bfloat16* dstb = is_q ? g_Qn : g_Kn;

    const float4* sA = (const float4*)(srcb + (size_t)r0 * D);
    const float4* sB = (const float4*)(srcb + (size_t)(r0 + 1) * D);
    float4 a0 = sA[lane * 2], a1 = sA[lane * 2 + 1];
    float4 b0 = sB[lane * 2], b1 = sB[lane * 2 + 1];

    float ssA = a0.x*a0.x + a0.y*a0.y + a0.z*a0.z + a0.w*a0.w
              + a1.x*a1.x + a1.y*a1.y + a1.z*a1.z + a1.w*a1.w;
    float ssB = b0.x*b0.x + b0.y*b0.y + b0.z*b0.z + b0.w*b0.w
              + b1.x*b1.x + b1.y*b1.y + b1.z*b1.z + b1.w*b1.w;
    #pragma unroll
    for (int o = 16; o > 0; o >>= 1) {               // two independent chains
        ssA += __shfl_xor_sync(0xffffffffu, ssA, o);
        ssB += __shfl_xor_sync(0xffffffffu, ssB, o);
    }

    float scA = rsqrtf(fmaxf(ssA, 1e-24f));
    float scB = rsqrtf(fmaxf(ssB, 1e-24f));
    if (is_q) { scA *= 2.0f * LOG2E; scB *= 2.0f * LOG2E; }

    uint4 oA, oB;
    {
        __nv_bfloat162 t0 = __float22bfloat162_rn({a0.x*scA, a0.y*scA});
        __nv_bfloat162 t1 = __float22bfloat162_rn({a0.z*scA, a0.w*scA});
        __nv_bfloat162 t2 = __float22bfloat162_rn({a1.x*scA, a1.y*scA});
        __nv_bfloat162 t3 = __float22bfloat162_rn({a1.z*scA, a1.w*scA});
        oA.x = *(uint32_t*)&t0; oA.y = *(uint32_t*)&t1;
        oA.z = *(uint32_t*)&t2; oA.w = *(uint32_t*)&t3;
    }
    {
        __nv_bfloat162 t0 = __float22bfloat162_rn({b0.x*scB, b0.y*scB});
        __nv_bfloat162 t1 = __float22bfloat162_rn({b0.z*scB, b0.w*scB});
        __nv_bfloat162 t2 = __float22bfloat162_rn({b1.x*scB, b1.y*scB});
        __nv_bfloat162 t3 = __float22bfloat162_rn({b1.z*scB, b1.w*scB});
        oB.x = *(uint32_t*)&t0; oB.y = *(uint32_t*)&t1;
        oB.z = *(uint32_t*)&t2; oB.w = *(uint32_t*)&t3;
    }
    ((uint4*)(dstb + (size_t)r0 * D))[lane]       = oA;
    ((uint4*)(dstb + (size_t)(r0 + 1) * D))[lane] = oB;
}

// ---------------------------------------------------------------------------
// Kernel 2: bf16 mma.sync GEMM + fused sum(2^logit). 256 thr (8 warps),
// warp grid 4(M) x 2(N), warp tile 32x64. mbarrier-paced double buffer.
// (R9 structure — batch epilogue; interleaved variants regressed twice.)
// ---------------------------------------------------------------------------
__global__ __launch_bounds__(THREADS, 1)
void infonce_kernel() {
    extern __shared__ __align__(16) char smem_raw[];
    const uint32_t sb = (uint32_t)__cvta_generic_to_shared(smem_raw);
    __nv_bfloat16* As  = (__nv_bfloat16*)(smem_raw + DATA_OFF); // 128 * SPAD
    __nv_bfloat16* Bs0 = As + BM * SPAD;                        // buf 0
    __nv_bfloat16* Bs1 = Bs0 + BN * SPAD;                       // buf 1
    __nv_bfloat16* Bbuf[2] = { Bs0, Bs1 };

    const uint32_t full_mb[2]  = { sb + MB_FULL0,  sb + MB_FULL1 };
    const uint32_t empty_mb[2] = { sb + MB_EMPTY0, sb + MB_EMPTY1 };

    const int tid    = threadIdx.x;
    const int lane   = tid & 31;
    const int warp   = tid >> 5;
    const int warp_m = warp >> 1;       // 0..3 (32 rows each)
    const int warp_n = warp & 1;        // 0..1 (64 cols each)

    const int qb    = blockIdx.x / KSPLIT;
    const int split = blockIdx.x % KSPLIT;
    const int qr0   = qb * BM;
    const int kv0   = split * NKEYS;

    if (tid == 0) {
        mbar_init(full_mb[0], THREADS);  mbar_init(full_mb[1], THREADS);
        mbar_init(empty_mb[0], 8);       mbar_init(empty_mb[1], 8);
    }
    __syncthreads();

    // prologue: A + tile0 -> buf0
    load_tile_async(As, g_Qn + (size_t)qr0 * D, tid);
    load_tile_async(Bs0, g_Kn + (size_t)kv0 * D, tid);
    cp_mbar_arrive_noinc(full_mb[0]);

    // ldmatrix addresses
    uint32_t a_base[2];
    #pragma unroll
    for (int mt = 0; mt < 2; ++mt)
        a_base[mt] = (uint32_t)__cvta_generic_to_shared(
            As + (warp_m * 32 + mt * 16 + (lane & 15)) * SPAD + (lane >> 4) * 8);
    uint32_t b_row_off[4];                // 4 x 16-col groups = 64 cols per warp
    #pragma unroll
    for (int b = 0; b < 4; ++b)
        b_row_off[b] = (uint32_t)(
            ((warp_n * 64 + b * 16 + ((lane >> 4) & 1) * 8 + (lane & 7)) * SPAD
             + ((lane >> 3) & 1) * 8) * sizeof(__nv_bfloat16));

    const bool cta_has_diag = (qr0 >= kv0) && (qr0 < kv0 + NKEYS);
    const int  kt_diag      = (qr0 - kv0) >> 7;

    // parities: full waits start {0,0}; empty waits start {0,1}
    uint32_t cf0 = 0, cf1 = 0, pe0 = 0, pe1 = 1;

    float rsum[4]  = {0.f, 0.f, 0.f, 0.f};
    float rdiag[4] = {0.f, 0.f, 0.f, 0.f};

    for (int kt = 0; kt < NT; ++kt) {
        const int b  = kt & 1;
        const int nb = b ^ 1;

        // producer: prefetch tile kt+1 into buf nb
        if (kt + 1 < NT) {
            uint32_t pe = nb ? pe1 : pe0;
            mbar_wait(empty_mb[nb], pe);
            if (nb) pe1 ^= 1; else pe0 ^= 1;
            load_tile_async(Bbuf[nb], g_Kn + (size_t)(kv0 + (kt + 1) * BN) * D, tid);
            cp_mbar_arrive_noinc(full_mb[nb]);
        }

        // consumer: tile kt data fully visible
        {
            uint32_t cf = b ? cf1 : cf0;
            mbar_wait(full_mb[b], cf);
            if (b) cf1 ^= 1; else cf0 ^= 1;
        }

        float acc[2][8][4];
        #pragma unroll
        for (int a = 0; a < 2; ++a)
            #pragma unroll
            for (int bb2 = 0; bb2 < 8; ++bb2)
                #pragma unroll
                for (int c = 0; c < 4; ++c) acc[a][bb2][c] = 0.f;

        const uint32_t bb = (uint32_t)__cvta_generic_to_shared(Bbuf[b]);

        #pragma unroll
        for (int ks = 0; ks < D / 16; ++ks) {
            uint32_t af[2][4], bf[16];
            ldsm_x4(af[0][0], af[0][1], af[0][2], af[0][3], a_base[0] + ks * 32);
            ldsm_x4(af[1][0], af[1][1], af[1][2], af[1][3], a_base[1] + ks * 32);
            #pragma unroll
            for (int g = 0; g < 4; ++g)
                ldsm_x4(bf[g * 4], bf[g * 4 + 1], bf[g * 4 + 2], bf[g * 4 + 3],
                        bb + b_row_off[g] + ks * 32);
            #pragma unroll
            for (int mt = 0; mt < 2; ++mt)
                #pragma unroll
                for (int nt = 0; nt < 8; ++nt) {
                    asm volatile(
                        "mma.sync.aligned.m16n8k16.row.col.f32.bf16.bf16.f32 "
                        "{%0,%1,%2,%3}, {%4,%5,%6,%7}, {%8,%9}, {%0,%1,%2,%3};\n"
                        : "+f"(acc[mt][nt][0]), "+f"(acc[mt][nt][1]),
                          "+f"(acc[mt][nt][2]), "+f"(acc[mt][nt][3])
                        : "r"(af[mt][0]), "r"(af[mt][1]),
                          "r"(af[mt][2]), "r"(af[mt][3]),
                          "r"(bf[nt * 2]), "r"(bf[nt * 2 + 1]));
                }
        }

        // done reading buf b -> producers may overwrite it (before epilogue)
        if (lane == 0) mbar_arrive(empty_mb[b]);

        // epilogue: 64 ex2 + adds (no max needed in log2 domain)
        #pragma unroll
        for (int mt = 0; mt < 2; ++mt)
            #pragma unroll
            for (int nt = 0; nt < 8; ++nt)
                #pragma unroll
                for (int c = 0; c < 4; ++c)
                    rsum[mt * 2 + (c >> 1)] += exp2_fast(acc[mt][nt][c]);

        if (cta_has_diag && kt == kt_diag) {
            #pragma unroll
            for (int mt = 0; mt < 2; ++mt)
                #pragma unroll
                for (int nt = 0; nt < 8; ++nt)
                    #pragma unroll
                    for (int c = 0; c < 4; ++c) {
                        int lr = warp_m * 32 + mt * 16 + (c >> 1) * 8 + (lane >> 2);
                        int lc = warp_n * 64 + nt * 8 + (lane & 3) * 2 + (c & 1);
                        if (lr == lc) rdiag[mt * 2 + (c >> 1)] += acc[mt][nt][c];
                    }
        }
    }

    // reduce: quad lanes share each row; then 2 n-warps per row via smem
    #pragma unroll
    for (int rs = 0; rs < 4; ++rs) {
        rsum[rs]  += __shfl_xor_sync(0xffffffffu, rsum[rs], 1);
        rsum[rs]  += __shfl_xor_sync(0xffffffffu, rsum[rs], 2);
        rdiag[rs] += __shfl_xor_sync(0xffffffffu, rdiag[rs], 1);
        rdiag[rs] += __shfl_xor_sync(0xffffffffu, rdiag[rs], 2);
    }
    __syncthreads();                       // B buffers free now
    float* s_sum = (float*)Bs0;            // [BM][2]
    float* s_dg  = s_sum + BM * 2;
    if ((lane & 3) == 0) {
        #pragma unroll
        for (int rs = 0; rs < 4; ++rs) {
            int lr = warp_m * 32 + (rs >> 1) * 16 + (rs & 1) * 8 + (lane >> 2);
            s_sum[lr * 2 + warp_n] = rsum[rs];
            s_dg [lr * 2 + warp_n] = rdiag[rs];
        }
    }
    __syncthreads();
    if (tid < BM) {
        float s = s_sum[tid * 2] + s_sum[tid * 2 + 1];
        float d = s_dg [tid * 2] + s_dg [tid * 2 + 1];
        int gr = qr0 + tid;
        g_psum [gr * KSPLIT + split] = s;
        g_pdiag[gr * KSPLIT + split] = d;
    }
}

// ---------------------------------------------------------------------------
// Kernel 3: finalize. loss = mean( ln2 * (log2(sum splits) - diag_log2) )
// ---------------------------------------------------------------------------
__global__ void finalize_kernel(float* __restrict__ out) {
    __shared__ float wsum[8];
    float acc = 0.f;
    for (int r = blockIdx.x * 256 + threadIdx.x; r < NMAX; r += gridDim.x * 256) {
        float s = 0.f, d = 0.f;
        #pragma unroll
        for (int k = 0; k < KSPLIT; ++k) {
            s += g_psum [r * KSPLIT + k];
            d += g_pdiag[r * KSPLIT + k];
        }
        acc += LN2 * (log2f(s) - d);
    }
    #pragma unroll
    for (int o = 16; o > 0; o >>= 1) acc += __shfl_xor_sync(0xffffffffu, acc, o);
    if ((threadIdx.x & 31) == 0) wsum[threadIdx.x >> 5] = acc;
    __syncthreads();
    if (threadIdx.x == 0) {
        float t = 0.f;
        #pragma unroll
        for (int i = 0; i < 8; ++i) t += wsum[i];
        atomicAdd(out, t / (float)NMAX);
    }
}

// ---------------------------------------------------------------------------
// Launch order (norm, infonce, memset, finalize): memset only needs to precede
// finalize's atomicAdd, and this ordering puts infonce at ncu's -s 5 slot so
// the profile finally captures the main kernel instead of normalize.
// ---------------------------------------------------------------------------
extern "C" void kernel_launch(void* const* d_in, const int* in_sizes, int n_in,
                              void* d_out, int out_size) {
    const float* q = (const float*)d_in[0];
    const float* k = (const float*)d_in[1];
    const int N = in_sizes[0] / D;          // 8192
    float* out = (float*)d_out;

    normalize_kernel<<<2 * N / 16, 256>>>(q, k, N);

    size_t smem = DATA_OFF + (size_t)(BM + 2 * BN) * SPAD * sizeof(__nv_bfloat16);
    cudaFuncSetAttribute(infonce_kernel,
                         cudaFuncAttributeMaxDynamicSharedMemorySize, (int)smem);
    infonce_kernel<<<GRID_SZ, THREADS, smem>>>();

    cudaMemsetAsync(out, 0, sizeof(float), 0);   // zero atomicAdd accumulator

    finalize_kernel<<<16, 256>>>(out);
}

// round 12
// speedup vs baseline: 1.1476x; 1.1041x over previous
#include <cuda_runtime.h>
#include <cuda_bf16.h>
#include <cstdint>

#define D        256
#define NMAX     8192
#define BM       128
#define BN       128
#define QBLKS    (NMAX / BM)             // 64
#define KTILES   (NMAX / BN)             // 64
#define TOT_TILES (QBLKS * KTILES)       // 4096
#define GRID_SZ  148                     // one CTA per SM, balanced static ranges
#define THREADS  256                     // 8 warps, warp grid 4(M) x 2(N)
#define SPAD     264                     // 256 + 8 halves pad: conflict-free LDSM

#define LOG2E    1.4426950408889634f
#define LN2      0.6931471805599453f

// smem: [0..31] mbarriers (full0, full1, empty0, empty1), data from 128
#define MB_FULL0   0
#define MB_FULL1   8
#define MB_EMPTY0  16
#define MB_EMPTY1  24
#define DATA_OFF   128

__device__ __align__(16) __nv_bfloat16 g_Qn[(size_t)NMAX * D];
__device__ __align__(16) __nv_bfloat16 g_Kn[(size_t)NMAX * D];
__device__ float g_psum[NMAX];
__device__ float g_pdiag[NMAX];

// ---------------- helpers ----------------
__device__ __forceinline__ void cp_async16(void* smem_dst, const void* gmem_src) {
    uint32_t s = (uint32_t)__cvta_generic_to_shared(smem_dst);
    asm volatile("cp.async.cg.shared.global [%0], [%1], 16;\n" :: "r"(s), "l"(gmem_src));
}
// .noinc: one REAL arrival per thread (init count == #threads).
__device__ __forceinline__ void cp_mbar_arrive_noinc(uint32_t mbar) {
    asm volatile("cp.async.mbarrier.arrive.noinc.shared::cta.b64 [%0];"
                 :: "r"(mbar) : "memory");
}
__device__ __forceinline__ void cp_wait_all() {
    asm volatile("cp.async.wait_group 0;\n" ::: "memory");
}
__device__ __forceinline__ void mbar_init(uint32_t a, uint32_t cnt) {
    asm volatile("mbarrier.init.shared.b64 [%0], %1;" :: "r"(a), "r"(cnt) : "memory");
}
__device__ __forceinline__ void mbar_arrive(uint32_t a) {
    asm volatile("mbarrier.arrive.shared.b64 _, [%0];" :: "r"(a) : "memory");
}
__device__ __forceinline__ void mbar_wait(uint32_t a, uint32_t parity) {
    asm volatile("{\n\t.reg .pred P1;\n\t"
                 "WAIT_LOOP_%=:\n\t"
                 "mbarrier.try_wait.parity.acquire.cta.shared::cta.b64 P1, [%0], %1, 0x989680;\n\t"
                 "@P1 bra.uni WAIT_DONE_%=;\n\t"
                 "bra.uni WAIT_LOOP_%=;\n\t"
                 "WAIT_DONE_%=:\n\t}" :: "r"(a), "r"(parity) : "memory");
}
__device__ __forceinline__ void ldsm_x4(uint32_t& r0, uint32_t& r1,
                                        uint32_t& r2, uint32_t& r3, uint32_t addr) {
    asm volatile("ldmatrix.sync.aligned.m8n8.x4.shared.b16 {%0,%1,%2,%3}, [%4];"
                 : "=r"(r0), "=r"(r1), "=r"(r2), "=r"(r3) : "r"(addr));
}
__device__ __forceinline__ float exp2_fast(float x) {
    float r;
    asm("ex2.approx.ftz.f32 %0, %1;" : "=f"(r) : "f"(x));
    return r;
}

// Load one [128 x 256 bf16] tile into SPAD-padded smem via cp.async (256 thr).
__device__ __forceinline__ void load_tile_async(__nv_bfloat16* s,
                                                const __nv_bfloat16* g, int tid) {
    const uint4* src = (const uint4*)g;
    #pragma unroll
    for (int i = tid; i < BM * 32; i += THREADS) {   // 32 x 16B chunks per row
        int r = i >> 5, c = i & 31;
        cp_async16(s + r * SPAD + c * 8, src + r * 32 + c);
    }
}

// ---------------------------------------------------------------------------
// Kernel 1: L2 normalize (one warp per TWO rows) + zero the partial arrays.
// Queries get 2*log2(e) folded in -> log2-domain logits, no max needed.
// ---------------------------------------------------------------------------
__global__ void normalize_kernel(const float* __restrict__ q,
                                 const float* __restrict__ k, int N) {
    // zero partial accumulators (ordering: same stream, before infonce)
    int gid = blockIdx.x * 256 + threadIdx.x;
    if (gid < NMAX) { g_psum[gid] = 0.f; g_pdiag[gid] = 0.f; }

    const int warp = threadIdx.x >> 5, lane = threadIdx.x & 31;
    const int row0 = blockIdx.x * 16 + warp * 2;     // grid = 2N/16
    const bool is_q = row0 < N;
    const int  r0   = is_q ? row0 : row0 - N;
    const float* srcb = is_q ? q : k;
    __nv_bfloat16* dstb = is_q ? g_Qn : g_Kn;

    const float4* sA = (const float4*)(srcb + (size_t)r0 * D);
    const float4* sB = (const float4*)(srcb + (size_t)(r0 + 1) * D);
    float4 a0 = sA[lane * 2], a1 = sA[lane * 2 + 1];
    float4 b0 = sB[lane * 2], b1 = sB[lane * 2 + 1];

    float ssA = a0.x*a0.x + a0.y*a0.y + a0.z*a0.z + a0.w*a0.w
              + a1.x*a1.x + a1.y*a1.y + a1.z*a1.z + a1.w*a1.w;
    float ssB = b0.x*b0.x + b0.y*b0.y + b0.z*b0.z + b0.w*b0.w
              + b1.x*b1.x + b1.y*b1.y + b1.z*b1.z + b1.w*b1.w;
    #pragma unroll
    for (int o = 16; o > 0; o >>= 1) {
        ssA += __shfl_xor_sync(0xffffffffu, ssA, o);
        ssB += __shfl_xor_sync(0xffffffffu, ssB, o);
    }

    float scA = rsqrtf(fmaxf(ssA, 1e-24f));
    float scB = rsqrtf(fmaxf(ssB, 1e-24f));
    if (is_q) { scA *= 2.0f * LOG2E; scB *= 2.0f * LOG2E; }

    uint4 oA, oB;
    {
        __nv_bfloat162 t0 = __float22bfloat162_rn({a0.x*scA, a0.y*scA});
        __nv_bfloat162 t1 = __float22bfloat162_rn({a0.z*scA, a0.w*scA});
        __nv_bfloat162 t2 = __float22bfloat162_rn({a1.x*scA, a1.y*scA});
        __nv_bfloat162 t3 = __float22bfloat162_rn({a1.z*scA, a1.w*scA});
        oA.x = *(uint32_t*)&t0; oA.y = *(uint32_t*)&t1;
        oA.z = *(uint32_t*)&t2; oA.w = *(uint32_t*)&t3;
    }
    {
        __nv_bfloat162 t0 = __float22bfloat162_rn({b0.x*scB, b0.y*scB});
        __nv_bfloat162 t1 = __float22bfloat162_rn({b0.z*scB, b0.w*scB});
        __nv_bfloat162 t2 = __float22bfloat162_rn({b1.x*scB, b1.y*scB});
        __nv_bfloat162 t3 = __float22bfloat162_rn({b1.z*scB, b1.w*scB});
        oB.x = *(uint32_t*)&t0; oB.y = *(uint32_t*)&t1;
        oB.z = *(uint32_t*)&t2; oB.w = *(uint32_t*)&t3;
    }
    ((uint4*)(dstb + (size_t)r0 * D))[lane]       = oA;
    ((uint4*)(dstb + (size_t)(r0 + 1) * D))[lane] = oB;
}

// ---------------------------------------------------------------------------
// Kernel 2: bf16 mma.sync GEMM + fused sum(2^logit). 148 CTAs; CTA i owns
// unit tiles [i*4096/148, (i+1)*4096/148) in qb-major order (27-28 tiles,
// perfectly balanced across all SMs; <=1 A-reload per CTA). Partials go to
// g_psum/g_pdiag[row] via fp32 atomicAdd. R9 pipeline/epilogue unchanged.
// ---------------------------------------------------------------------------
__global__ __launch_bounds__(THREADS, 1)
void infonce_kernel() {
    extern __shared__ __align__(16) char smem_raw[];
    const uint32_t sb = (uint32_t)__cvta_generic_to_shared(smem_raw);
    __nv_bfloat16* As  = (__nv_bfloat16*)(smem_raw + DATA_OFF); // 128 * SPAD
    __nv_bfloat16* Bs0 = As + BM * SPAD;                        // buf 0
    __nv_bfloat16* Bs1 = Bs0 + BN * SPAD;                       // buf 1
    __nv_bfloat16* Bbuf[2] = { Bs0, Bs1 };

    const uint32_t full_mb[2]  = { sb + MB_FULL0,  sb + MB_FULL1 };
    const uint32_t empty_mb[2] = { sb + MB_EMPTY0, sb + MB_EMPTY1 };

    const int tid    = threadIdx.x;
    const int lane   = tid & 31;
    const int warp   = tid >> 5;
    const int warp_m = warp >> 1;       // 0..3 (32 rows each)
    const int warp_n = warp & 1;        // 0..1 (64 cols each)

    const int start = (blockIdx.x * TOT_TILES) / GRID_SZ;
    const int end   = ((blockIdx.x + 1) * TOT_TILES) / GRID_SZ;
    int cur_qb = start >> 6;

    if (tid == 0) {
        mbar_init(full_mb[0], THREADS);  mbar_init(full_mb[1], THREADS);
        mbar_init(empty_mb[0], 8);       mbar_init(empty_mb[1], 8);
    }
    __syncthreads();

    // prologue: A(cur_qb) + B(kt(start)) -> buf0
    load_tile_async(As, g_Qn + (size_t)cur_qb * BM * D, tid);
    load_tile_async(Bs0, g_Kn + (size_t)(start & 63) * BN * D, tid);
    cp_mbar_arrive_noinc(full_mb[0]);

    // ldmatrix addresses (A smem location fixed; contents swap per qb)
    uint32_t a_base[2];
    #pragma unroll
    for (int mt = 0; mt < 2; ++mt)
        a_base[mt] = (uint32_t)__cvta_generic_to_shared(
            As + (warp_m * 32 + mt * 16 + (lane & 15)) * SPAD + (lane >> 4) * 8);
    uint32_t b_row_off[4];                // 4 x 16-col groups = 64 cols per warp
    #pragma unroll
    for (int b = 0; b < 4; ++b)
        b_row_off[b] = (uint32_t)(
            ((warp_n * 64 + b * 16 + ((lane >> 4) & 1) * 8 + (lane & 7)) * SPAD
             + ((lane >> 3) & 1) * 8) * sizeof(__nv_bfloat16));

    // parities: full waits start {0,0}; empty waits start {0,1}
    uint32_t cf0 = 0, cf1 = 0, pe0 = 0, pe1 = 1;

    float rsum[4]  = {0.f, 0.f, 0.f, 0.f};
    float rdiag[4] = {0.f, 0.f, 0.f, 0.f};

    // flush partials of qb via quad-shfl + global atomicAdd, then zero
    auto flush_partials = [&](int qb) {
        #pragma unroll
        for (int rs = 0; rs < 4; ++rs) {
            rsum[rs]  += __shfl_xor_sync(0xffffffffu, rsum[rs], 1);
            rsum[rs]  += __shfl_xor_sync(0xffffffffu, rsum[rs], 2);
            rdiag[rs] += __shfl_xor_sync(0xffffffffu, rdiag[rs], 1);
            rdiag[rs] += __shfl_xor_sync(0xffffffffu, rdiag[rs], 2);
        }
        if ((lane & 3) == 0) {
            #pragma unroll
            for (int rs = 0; rs < 4; ++rs) {
                int row = qb * BM + warp_m * 32 + (rs >> 1) * 16
                        + (rs & 1) * 8 + (lane >> 2);
                atomicAdd(&g_psum[row], rsum[rs]);
                atomicAdd(&g_pdiag[row], rdiag[rs]);
            }
        }
        #pragma unroll
        for (int rs = 0; rs < 4; ++rs) { rsum[rs] = 0.f; rdiag[rs] = 0.f; }
    };

    for (int t = start; t < end; ++t) {
        const int j  = t - start;
        const int qb = t >> 6;
        const int kt = t & 63;
        const int b  = j & 1;
        const int nb = b ^ 1;

        // qb transition (at most once per CTA): flush rows, reload A
        if (qb != cur_qb) {
            flush_partials(cur_qb);
            __syncthreads();     // all warps done with MMA on old A
            load_tile_async(As, g_Qn + (size_t)qb * BM * D, tid);
            cp_wait_all();       // A cps (+ any in-flight B(t) cps) complete
            __syncthreads();
            cur_qb = qb;
        }

        // producer: prefetch B of tile t+1 into buf nb
        if (t + 1 < end) {
            uint32_t pe = nb ? pe1 : pe0;
            mbar_wait(empty_mb[nb], pe);
            if (nb) pe1 ^= 1; else pe0 ^= 1;
            load_tile_async(Bbuf[nb],
                            g_Kn + (size_t)((t + 1) & 63) * BN * D, tid);
            cp_mbar_arrive_noinc(full_mb[nb]);
        }

        // consumer: tile t's B (and A) fully visible
        {
            uint32_t cf = b ? cf1 : cf0;
            mbar_wait(full_mb[b], cf);
            if (b) cf1 ^= 1; else cf0 ^= 1;
        }

        float acc[2][8][4];
        #pragma unroll
        for (int a = 0; a < 2; ++a)
            #pragma unroll
            for (int bb2 = 0; bb2 < 8; ++bb2)
                #pragma unroll
                for (int c = 0; c < 4; ++c) acc[a][bb2][c] = 0.f;

        const uint32_t bb = (uint32_t)__cvta_generic_to_shared(Bbuf[b]);

        #pragma unroll
        for (int ks = 0; ks < D / 16; ++ks) {
            uint32_t af[2][4], bf[16];
            ldsm_x4(af[0][0], af[0][1], af[0][2], af[0][3], a_base[0] + ks * 32);
            ldsm_x4(af[1][0], af[1][1], af[1][2], af[1][3], a_base[1] + ks * 32);
            #pragma unroll
            for (int g = 0; g < 4; ++g)
                ldsm_x4(bf[g * 4], bf[g * 4 + 1], bf[g * 4 + 2], bf[g * 4 + 3],
                        bb + b_row_off[g] + ks * 32);
            #pragma unroll
            for (int mt = 0; mt < 2; ++mt)
                #pragma unroll
                for (int nt = 0; nt < 8; ++nt) {
                    asm volatile(
                        "mma.sync.aligned.m16n8k16.row.col.f32.bf16.bf16.f32 "
                        "{%0,%1,%2,%3}, {%4,%5,%6,%7}, {%8,%9}, {%0,%1,%2,%3};\n"
                        : "+f"(acc[mt][nt][0]), "+f"(acc[mt][nt][1]),
                          "+f"(acc[mt][nt][2]), "+f"(acc[mt][nt][3])
                        : "r"(af[mt][0]), "r"(af[mt][1]),
                          "r"(af[mt][2]), "r"(af[mt][3]),
                          "r"(bf[nt * 2]), "r"(bf[nt * 2 + 1]));
                }
        }

        // done reading buf b -> producers may overwrite it (before epilogue)
        if (lane == 0) mbar_arrive(empty_mb[b]);

        // epilogue: 64 ex2 + adds (no max needed in log2 domain)
        #pragma unroll
        for (int mt = 0; mt < 2; ++mt)
            #pragma unroll
            for (int nt = 0; nt < 8; ++nt)
                #pragma unroll
                for (int c = 0; c < 4; ++c)
                    rsum[mt * 2 + (c >> 1)] += exp2_fast(acc[mt][nt][c]);

        // diagonal lives exactly in the kt == qb tile
        if (kt == qb) {
            #pragma unroll
            for (int mt = 0; mt < 2; ++mt)
                #pragma unroll
                for (int nt = 0; nt < 8; ++nt)
                    #pragma unroll
                    for (int c = 0; c < 4; ++c) {
                        int lr = warp_m * 32 + mt * 16 + (c >> 1) * 8 + (lane >> 2);
                        int lc = warp_n * 64 + nt * 8 + (lane & 3) * 2 + (c & 1);
                        if (lr == lc) rdiag[mt * 2 + (c >> 1)] += acc[mt][nt][c];
                    }
        }
    }

    flush_partials(cur_qb);
}

// ---------------------------------------------------------------------------
// Kernel 3: finalize. loss = mean( ln2 * (log2(rowsum) - diag_log2) )
// ---------------------------------------------------------------------------
__global__ void finalize_kernel(float* __restrict__ out) {
    __shared__ float wsum[8];
    float acc = 0.f;
    for (int r = blockIdx.x * 256 + threadIdx.x; r < NMAX; r += gridDim.x * 256)
        acc += LN2 * (log2f(g_psum[r]) - g_pdiag[r]);
    #pragma unroll
    for (int o = 16; o > 0; o >>= 1) acc += __shfl_xor_sync(0xffffffffu, acc, o);
    if ((threadIdx.x & 31) == 0) wsum[threadIdx.x >> 5] = acc;
    __syncthreads();
    if (threadIdx.x == 0) {
        float t = 0.f;
        #pragma unroll
        for (int i = 0; i < 8; ++i) t += wsum[i];
        atomicAdd(out, t / (float)NMAX);
    }
}

// ---------------------------------------------------------------------------
extern "C" void kernel_launch(void* const* d_in, const int* in_sizes, int n_in,
                              void* d_out, int out_size) {
    const float* q = (const float*)d_in[0];
    const float* k = (const float*)d_in[1];
    const int N = in_sizes[0] / D;          // 8192
    float* out = (float*)d_out;

    normalize_kernel<<<2 * N / 16, 256>>>(q, k, N);

    size_t smem = DATA_OFF + (size_t)(BM + 2 * BN) * SPAD * sizeof(__nv_bfloat16);
    cudaFuncSetAttribute(infonce_kernel,
                         cudaFuncAttributeMaxDynamicSharedMemorySize, (int)smem);
    infonce_kernel<<<GRID_SZ, THREADS, smem>>>();

    cudaMemsetAsync(out, 0, sizeof(float), 0);   // zero atomicAdd accumulator

    finalize_kernel<<<16, 256>>>(out);
}